// round 5
// baseline (speedup 1.0000x reference)
#include <cuda_runtime.h>
#include <cstdint>

// Problem constants
constexpr int B_TOT = 16384;
constexpr int F = 40;
constexpr int D = 32;
constexpr int NB = 8;                  // batches per CTA

// Padded shared strides (all j-strides ≡ 8 (mod 32) -> half-warp 2-address
// broadcasts hit different banks)
constexpr int HS  = 1288;              // h_s per-j stride (floats), 1288 % 32 = 8
constexpr int GS  = 1600;              // g_s per-j stride (natural, contiguous)
constexpr int HOS = 648;               // hout2 per-j stride (float2 units)
constexpr int AFS = 33;                // aggr per-field stride (pad 1)
constexpr int AS  = F * AFS;           // 1320, % 32 = 8

// smem layout (floats):
//   h_s   : NB*HS          = 10304
//   g_s   : NB*GS          = 12800
//   ho_s  : NB*HOS*2       = 10368   (float2 pairs (d, d+16))
//   a_s   : NB*AS          = 10560
constexpr int SMEM_FLOATS = NB * HS + NB * GS + NB * HOS * 2 + NB * AS;  // 44032
constexpr int SMEM_BYTES  = SMEM_FLOATS * 4;                              // 176128

// ---------------- f32x2 helpers ----------------
__device__ __forceinline__ unsigned long long pack2(float lo, float hi) {
    unsigned long long r;
    asm("mov.b64 %0, {%1, %2};" : "=l"(r) : "f"(lo), "f"(hi));
    return r;
}
__device__ __forceinline__ void unpack2(unsigned long long v, float& lo, float& hi) {
    asm("mov.b64 {%0, %1}, %2;" : "=f"(lo), "=f"(hi) : "l"(v));
}
__device__ __forceinline__ unsigned long long ffma2(unsigned long long a,
                                                    unsigned long long b,
                                                    unsigned long long c) {
    unsigned long long d;
    asm("fma.rn.f32x2 %0, %1, %2, %3;" : "=l"(d) : "l"(a), "l"(b), "l"(c));
    return d;
}

__global__ void __launch_bounds__(256, 1)
graphlayer_kernel(const float* __restrict__ g,
                  const float* __restrict__ h,
                  const float* __restrict__ W_in,
                  const float* __restrict__ W_out,
                  const float* __restrict__ bias_p,
                  float* __restrict__ out)
{
    extern __shared__ float smem[];
    float*              h_s  = smem;                                   // [8][HS]
    float*              g_s  = smem + NB * HS;                         // [8][GS]
    unsigned long long* ho_s = (unsigned long long*)(smem + NB * HS + NB * GS); // [8][HOS]
    float*              a_s  = smem + NB * HS + NB * GS + NB * HOS * 2;// [8][AS]

    const int tid  = threadIdx.x;
    const int lane = tid & 31;
    const int warp = tid >> 5;          // 8 warps
    const int half = lane >> 4;         // 0/1 (half-warp id)
    const int hl   = lane & 15;         // d0 = hl, d1 = hl + 16
    const long b0  = (long)blockIdx.x * NB;

    // ---------------- Stage 0: stage h (padded per-j) and g (linear) ----------------
    {
        // warp = j : copy 1280 floats of h into padded row
        const float4* hsrc = (const float4*)(h + (b0 + warp) * (F * D));
        float*        hdst = h_s + warp * HS;
        #pragma unroll
        for (int i = 0; i < 10; i++) {
            float4 v = hsrc[lane + i * 32];
            *(float4*)(hdst + (lane + i * 32) * 4) = v;
        }
        // g: 12800 floats linear copy (GS == F*F, contiguous)
        const float4* gsrc = (const float4*)(g + b0 * (F * F));
        float4*       gdst = (float4*)g_s;
        #pragma unroll
        for (int i = 0; i < 13; i++) {
            int idx = tid + i * 256;
            if (idx < 3200) gdst[idx] = gsrc[idx];
        }
    }
    __syncthreads();

    // ---------------- Stage 1: hout[j][f][d] = sum_e W_out[f][d][e] * h[j][f][e] ----------------
    // warp w owns f in {w, w+8, ..., w+32}; lane: (half = j-parity, hl = d-pair)
    #pragma unroll 1
    for (int k = 0; k < 5; k++) {
        const int f = warp + k * 8;
        const float* wa = W_out + (f * D + hl) * D;        // row d0
        const float* wb = W_out + (f * D + hl + 16) * D;   // row d1
        unsigned long long acc[4];
        #pragma unroll
        for (int jp = 0; jp < 4; jp++) acc[jp] = 0ull;

        #pragma unroll
        for (int ec = 0; ec < 4; ec++) {
            const float4 a0 = *(const float4*)(wa + ec * 8);
            const float4 a1 = *(const float4*)(wa + ec * 8 + 4);
            const float4 b4 = *(const float4*)(wb + ec * 8);
            const float4 b5 = *(const float4*)(wb + ec * 8 + 4);
            unsigned long long w2[8];
            w2[0] = pack2(a0.x, b4.x); w2[1] = pack2(a0.y, b4.y);
            w2[2] = pack2(a0.z, b4.z); w2[3] = pack2(a0.w, b4.w);
            w2[4] = pack2(a1.x, b5.x); w2[5] = pack2(a1.y, b5.y);
            w2[6] = pack2(a1.z, b5.z); w2[7] = pack2(a1.w, b5.w);
            #pragma unroll
            for (int jp = 0; jp < 4; jp++) {
                const float* hp = h_s + (2 * jp + half) * HS + f * 32 + ec * 8;
                #pragma unroll
                for (int e = 0; e < 8; e++) {
                    const float hv = hp[e];
                    acc[jp] = ffma2(w2[e], pack2(hv, hv), acc[jp]);
                }
            }
        }
        // store pre-packed (d0, d1) pairs for stage 2
        #pragma unroll
        for (int jp = 0; jp < 4; jp++) {
            const int j = 2 * jp + half;
            ho_s[j * HOS + f * 16 + hl] = acc[jp];
        }
    }
    __syncthreads();

    // ---------------- Stage 2: aggr[j][f][d] = sum_g g[j][f][gi] * hout[j][gi][d] ----------------
    // warp = j; half-warps = field pair (f = 2*fp + half); lanes = d-pairs; hout in regs
    {
        const int j = warp;
        const float* grow = g_s + j * GS;
        unsigned long long acc[20];
        #pragma unroll
        for (int fp = 0; fp < 20; fp++) acc[fp] = 0ull;

        #pragma unroll
        for (int c = 0; c < 2; c++) {           // gi chunks of 20
            unsigned long long hreg[20];
            #pragma unroll
            for (int t = 0; t < 20; t++)
                hreg[t] = ho_s[j * HOS + (c * 20 + t) * 16 + hl];
            #pragma unroll
            for (int fp = 0; fp < 20; fp++) {
                const int f = fp * 2 + half;
                const float* gp = grow + f * F + c * 20;
                #pragma unroll
                for (int t = 0; t < 20; t++) {
                    const float gv = gp[t];
                    acc[fp] = ffma2(pack2(gv, gv), hreg[t], acc[fp]);
                }
            }
        }
        // store aggr scalar with padded field stride (for stage-3 broadcasts)
        #pragma unroll
        for (int fp = 0; fp < 20; fp++) {
            const int f = fp * 2 + half;
            float lo, hi; unpack2(acc[fp], lo, hi);
            a_s[j * AS + f * AFS + hl]      = lo;
            a_s[j * AS + f * AFS + hl + 16] = hi;
        }
    }
    __syncthreads();

    // ---------------- Stage 3: out[j][f][d] = sum_e W_in[f][d][e] * aggr[j][f][e] + bias ----------------
    const float bias0 = __ldg(bias_p + hl);
    const float bias1 = __ldg(bias_p + hl + 16);
    #pragma unroll 1
    for (int k = 0; k < 5; k++) {
        const int f = warp + k * 8;
        const float* wa = W_in + (f * D + hl) * D;
        const float* wb = W_in + (f * D + hl + 16) * D;
        unsigned long long acc[4];
        #pragma unroll
        for (int jp = 0; jp < 4; jp++) acc[jp] = 0ull;

        #pragma unroll
        for (int ec = 0; ec < 4; ec++) {
            const float4 a0 = *(const float4*)(wa + ec * 8);
            const float4 a1 = *(const float4*)(wa + ec * 8 + 4);
            const float4 b4 = *(const float4*)(wb + ec * 8);
            const float4 b5 = *(const float4*)(wb + ec * 8 + 4);
            unsigned long long w2[8];
            w2[0] = pack2(a0.x, b4.x); w2[1] = pack2(a0.y, b4.y);
            w2[2] = pack2(a0.z, b4.z); w2[3] = pack2(a0.w, b4.w);
            w2[4] = pack2(a1.x, b5.x); w2[5] = pack2(a1.y, b5.y);
            w2[6] = pack2(a1.z, b5.z); w2[7] = pack2(a1.w, b5.w);
            #pragma unroll
            for (int jp = 0; jp < 4; jp++) {
                const float* ap = a_s + (2 * jp + half) * AS + f * AFS + ec * 8;
                #pragma unroll
                for (int e = 0; e < 8; e++) {
                    const float av = ap[e];
                    acc[jp] = ffma2(w2[e], pack2(av, av), acc[jp]);
                }
            }
        }
        #pragma unroll
        for (int jp = 0; jp < 4; jp++) {
            const int j = 2 * jp + half;
            float lo, hi; unpack2(acc[jp], lo, hi);
            float* op = out + (b0 + j) * (F * D) + f * D;
            op[hl]      = lo + bias0;
            op[hl + 16] = hi + bias1;
        }
    }
}

extern "C" void kernel_launch(void* const* d_in, const int* in_sizes, int n_in,
                              void* d_out, int out_size)
{
    (void)in_sizes; (void)n_in; (void)out_size;
    const float* g     = (const float*)d_in[0];
    const float* h     = (const float*)d_in[1];
    const float* W_in  = (const float*)d_in[2];
    const float* W_out = (const float*)d_in[3];
    const float* bias  = (const float*)d_in[4];
    float* out = (float*)d_out;

    cudaFuncSetAttribute(graphlayer_kernel,
                         cudaFuncAttributeMaxDynamicSharedMemorySize, SMEM_BYTES);

    graphlayer_kernel<<<B_TOT / NB, 256, SMEM_BYTES>>>(g, h, W_in, W_out, bias, out);
}

// round 6
// speedup vs baseline: 1.9833x; 1.9833x over previous
#include <cuda_runtime.h>
#include <cstdint>

// Problem constants
constexpr int B_TOT = 16384;
constexpr int F = 40;
constexpr int D = 32;
constexpr int NB = 16;                 // batches per CTA
constexpr int GRID = B_TOT / NB;       // 1024

// Shared strides (floats)
constexpr int HSTR  = 1284;            // h rows      (1284 % 32 == 4)
constexpr int HOSTR = 1444;            // hout/aggr   (1444 % 32 == 4)
constexpr int GSTR  = 1600;            // g rows (natural, contiguous)
constexpr int AFS   = 36;              // aggr f-stride (36 % 32 == 4)

// smem offsets (floats)
constexpr int OH  = 0;                     // h:    16*1284 = 20544
constexpr int OHO = OH + NB * HSTR;        // ho:   16*1444 = 23104
constexpr int OG  = OHO + NB * HOSTR;      // g:     8*1600 = 12800
constexpr int OMB = OG + 8 * GSTR;         // mbarriers (3 x u64)
constexpr int SMEM_BYTES = (OMB + 8) * 4;  // 225824 B

// W transpose scratch: [0..40) Wout_t, [40..80) Win_t, each [f][e][d]
__device__ float g_Wt[2 * 40 * 1024];

// ---------------- helpers ----------------
__device__ __forceinline__ unsigned long long pack2(float v) {
    unsigned long long r;
    asm("mov.b64 %0, {%1, %1};" : "=l"(r) : "f"(v));
    return r;
}
__device__ __forceinline__ unsigned long long ffma2(unsigned long long a,
                                                    unsigned long long b,
                                                    unsigned long long c) {
    unsigned long long d;
    asm("fma.rn.f32x2 %0, %1, %2, %3;" : "=l"(d) : "l"(a), "l"(b), "l"(c));
    return d;
}
__device__ __forceinline__ uint32_t smem_u32(const void* p) {
    return (uint32_t)__cvta_generic_to_shared(p);
}
__device__ __forceinline__ void mbar_init(uint32_t mbar, uint32_t cnt) {
    asm volatile("mbarrier.init.shared.b64 [%0], %1;" :: "r"(mbar), "r"(cnt) : "memory");
}
__device__ __forceinline__ void mbar_expect_tx(uint32_t mbar, uint32_t bytes) {
    asm volatile("mbarrier.arrive.expect_tx.shared.b64 _, [%0], %1;"
                 :: "r"(mbar), "r"(bytes) : "memory");
}
__device__ __forceinline__ void mbar_wait(uint32_t mbar, uint32_t parity) {
    uint32_t done;
    asm volatile(
        "{\n\t.reg .pred p;\n\t"
        "mbarrier.try_wait.parity.acquire.cta.shared::cta.b64 p, [%1], %2;\n\t"
        "selp.b32 %0, 1, 0, p;\n\t}"
        : "=r"(done) : "r"(mbar), "r"(parity) : "memory");
    if (!done) {
        asm volatile(
            "{\n\t.reg .pred P1;\n\t"
            "W_%=:\n\t"
            "mbarrier.try_wait.parity.acquire.cta.shared::cta.b64 P1, [%0], %1, 0x989680;\n\t"
            "@P1 bra.uni DONE_%=;\n\t"
            "bra.uni W_%=;\n\t"
            "DONE_%=:\n\t}"
            :: "r"(mbar), "r"(parity) : "memory");
    }
}
__device__ __forceinline__ void bulk_copy(uint32_t dst_smem, const void* src,
                                          uint32_t bytes, uint32_t mbar) {
    asm volatile(
        "cp.async.bulk.shared::cluster.global.mbarrier::complete_tx::bytes "
        "[%0], [%1], %2, [%3];"
        :: "r"(dst_smem), "l"(src), "r"(bytes), "r"(mbar) : "memory");
}

// ---------------- W transpose prologue ----------------
__global__ void __launch_bounds__(1024)
transposeW_kernel(const float* __restrict__ W_in, const float* __restrict__ W_out)
{
    __shared__ float t[32][33];
    const int b = blockIdx.x;                         // 0..79
    const float* src = (b < 40) ? (W_out + b * 1024) : (W_in + (b - 40) * 1024);
    float* dst = g_Wt + b * 1024;
    const int c = threadIdx.x & 31;
    const int r = threadIdx.x >> 5;
    t[r][c] = src[r * 32 + c];       // t[d][e] = W[d][e]
    __syncthreads();
    dst[r * 32 + c] = t[c][r];       // Wt[e][d] = W[d][e]
}

// ---------------- main fused kernel ----------------
__global__ void __launch_bounds__(256, 1)
graphlayer_kernel(const float* __restrict__ g,
                  const float* __restrict__ h,
                  const float* __restrict__ bias_p,
                  float* __restrict__ out)
{
    extern __shared__ float smem[];
    float* h_s  = smem + OH;
    float* hoag = smem + OHO;
    float* g_s  = smem + OG;

    const int tid  = threadIdx.x;
    const int lane = tid & 31;
    const int warp = tid >> 5;
    const long b0  = (long)blockIdx.x * NB;

    const uint32_t mb_h  = smem_u32(smem + OMB);
    const uint32_t mb_g1 = mb_h + 8;
    const uint32_t mb_g2 = mb_h + 16;

    if (tid == 0) {
        mbar_init(mb_h, 1);
        mbar_init(mb_g1, 1);
        mbar_init(mb_g2, 1);
    }
    __syncthreads();

    if (tid == 0) {
        // h: 16 rows of 5120B into padded smem rows
        mbar_expect_tx(mb_h, NB * F * D * 4);
        const uint32_t hdst = smem_u32(h_s);
        #pragma unroll
        for (int j = 0; j < NB; j++)
            bulk_copy(hdst + j * HSTR * 4, h + (b0 + j) * (F * D), F * D * 4, mb_h);
        // g chunk 1 (j = 0..7)
        mbar_expect_tx(mb_g1, 8 * F * F * 4);
        const uint32_t gdst = smem_u32(g_s);
        #pragma unroll
        for (int j = 0; j < 8; j++)
            bulk_copy(gdst + j * GSTR * 4, g + (b0 + j) * (F * F), F * F * 4, mb_g1);
    }

    const float* WoutT = g_Wt;
    const float* WinT  = g_Wt + 40 * 1024;

    const int jg = lane >> 3;          // 0..3
    const int dg = lane & 7;           // 0..7

    mbar_wait(mb_h, 0);

    // ---------------- Stage 1: hout[j][f][d] = sum_e Wout[f][d][e] h[j][f][e] ----------------
    #pragma unroll 1
    for (int k = 0; k < 5; k++) {
        const int f = warp + k * 8;
        const float* wt = WoutT + f * 1024 + dg * 4;
        float4 acc[4] = {};
        #pragma unroll 4
        for (int e = 0; e < 32; e++) {
            const float4 wv = __ldg((const float4*)(wt + e * 32));
            #pragma unroll
            for (int jt = 0; jt < 4; jt++) {
                const float xv = h_s[(jg + 4 * jt) * HSTR + f * 32 + e];
                acc[jt].x += xv * wv.x;  acc[jt].y += xv * wv.y;
                acc[jt].z += xv * wv.z;  acc[jt].w += xv * wv.w;
            }
        }
        #pragma unroll
        for (int jt = 0; jt < 4; jt++)
            *(float4*)&hoag[(jg + 4 * jt) * HOSTR + f * 32 + dg * 4] = acc[jt];
    }
    __syncthreads();

    // prefetch g chunk 2 into the (now free) h region
    if (tid == 0) {
        mbar_expect_tx(mb_g2, 8 * F * F * 4);
        const uint32_t gdst2 = smem_u32(h_s);
        #pragma unroll
        for (int j = 0; j < 8; j++)
            bulk_copy(gdst2 + j * GSTR * 4, g + (b0 + 8 + j) * (F * F), F * F * 4, mb_g2);
    }

    // ---------------- Stage 2: aggr[j][f][d] = sum_gi g[j][f][gi] hout[j][gi][d] ----------------
    const int fg = lane >> 3;          // 0..3
    const int dm = lane & 7;           // d pairs: (2dm,2dm+1) and (+16)
    #pragma unroll 1
    for (int half = 0; half < 2; half++) {
        if (half == 0) mbar_wait(mb_g1, 0);
        else           mbar_wait(mb_g2, 0);
        const int jj = warp + half * 8;
        const float* gj  = (half == 0 ? g_s : h_s) + warp * GSTR;
        float*       hob = hoag + jj * HOSTR;

        unsigned long long acc[10][2];
        #pragma unroll
        for (int ft = 0; ft < 10; ft++) { acc[ft][0] = 0ull; acc[ft][1] = 0ull; }

        #pragma unroll 2
        for (int gi = 0; gi < F; gi++) {
            const unsigned long long ho0 = *(const unsigned long long*)(hob + gi * 32 + dm * 2);
            const unsigned long long ho1 = *(const unsigned long long*)(hob + gi * 32 + dm * 2 + 16);
            #pragma unroll
            for (int ft = 0; ft < 10; ft++) {
                const unsigned long long g2 = pack2(gj[(fg + 4 * ft) * F + gi]);
                acc[ft][0] = ffma2(g2, ho0, acc[ft][0]);
                acc[ft][1] = ffma2(g2, ho1, acc[ft][1]);
            }
        }
        // write aggr in place (ho row fully consumed; only this warp owns row jj)
        #pragma unroll
        for (int ft = 0; ft < 10; ft++) {
            const int f = fg + 4 * ft;
            *(unsigned long long*)(hob + f * AFS + dm * 2)      = acc[ft][0];
            *(unsigned long long*)(hob + f * AFS + dm * 2 + 16) = acc[ft][1];
        }
    }
    __syncthreads();

    // ---------------- Stage 3: out[j][f][d] = sum_e Win[f][d][e] aggr[j][f][e] + bias ----------------
    const float4 bias4 = __ldg((const float4*)(bias_p + dg * 4));
    #pragma unroll 1
    for (int k = 0; k < 5; k++) {
        const int f = warp + k * 8;
        const float* wt = WinT + f * 1024 + dg * 4;
        float4 acc[4] = {};
        #pragma unroll 4
        for (int e = 0; e < 32; e++) {
            const float4 wv = __ldg((const float4*)(wt + e * 32));
            #pragma unroll
            for (int jt = 0; jt < 4; jt++) {
                const float xv = hoag[(jg + 4 * jt) * HOSTR + f * AFS + e];
                acc[jt].x += xv * wv.x;  acc[jt].y += xv * wv.y;
                acc[jt].z += xv * wv.z;  acc[jt].w += xv * wv.w;
            }
        }
        #pragma unroll
        for (int jt = 0; jt < 4; jt++) {
            float4 r = acc[jt];
            r.x += bias4.x; r.y += bias4.y; r.z += bias4.z; r.w += bias4.w;
            *(float4*)&out[(b0 + jg + 4 * jt) * (F * D) + f * 32 + dg * 4] = r;
        }
    }
}

extern "C" void kernel_launch(void* const* d_in, const int* in_sizes, int n_in,
                              void* d_out, int out_size)
{
    (void)in_sizes; (void)n_in; (void)out_size;
    const float* g     = (const float*)d_in[0];
    const float* h     = (const float*)d_in[1];
    const float* W_in  = (const float*)d_in[2];
    const float* W_out = (const float*)d_in[3];
    const float* bias  = (const float*)d_in[4];
    float* out = (float*)d_out;

    cudaFuncSetAttribute(graphlayer_kernel,
                         cudaFuncAttributeMaxDynamicSharedMemorySize, SMEM_BYTES);

    transposeW_kernel<<<80, 1024>>>(W_in, W_out);
    graphlayer_kernel<<<GRID, 256, SMEM_BYTES>>>(g, h, bias, out);
}

// round 7
// speedup vs baseline: 2.6819x; 1.3522x over previous
#include <cuda_runtime.h>
#include <cstdint>

// Problem constants
constexpr int B_TOT = 16384;
constexpr int F = 40;
constexpr int D = 32;
constexpr int NB = 16;                 // batches per CTA
constexpr int GRID = B_TOT / NB;       // 1024
constexpr int NTHREADS = 512;          // 16 warps

// Shared strides (floats)
constexpr int HSTR  = 1284;            // h rows      (1284 % 32 == 4)
constexpr int HOSTR = 1444;            // hout/aggr   (1444 % 32 == 4)
constexpr int GSTR  = 1600;            // g rows (natural, contiguous)
constexpr int AFS   = 36;              // aggr f-stride (36 % 32 == 4)

// smem offsets (floats)
constexpr int OH  = 0;                     // h:    16*1284 = 20544
constexpr int OHO = OH + NB * HSTR;        // ho:   16*1444 = 23104
constexpr int OG  = OHO + NB * HOSTR;      // g:     8*1600 = 12800
constexpr int OMB = OG + 8 * GSTR;         // mbarriers (3 x u64)
constexpr int SMEM_BYTES = (OMB + 8) * 4;  // 225824 B

// W transpose scratch: [0..40) Wout_t, [40..80) Win_t, each [f][e][d]
__device__ float g_Wt[2 * 40 * 1024];

// ---------------- helpers ----------------
__device__ __forceinline__ unsigned long long pack2(float v) {
    unsigned long long r;
    asm("mov.b64 %0, {%1, %1};" : "=l"(r) : "f"(v));
    return r;
}
__device__ __forceinline__ unsigned long long ffma2(unsigned long long a,
                                                    unsigned long long b,
                                                    unsigned long long c) {
    unsigned long long d;
    asm("fma.rn.f32x2 %0, %1, %2, %3;" : "=l"(d) : "l"(a), "l"(b), "l"(c));
    return d;
}
__device__ __forceinline__ uint32_t smem_u32(const void* p) {
    return (uint32_t)__cvta_generic_to_shared(p);
}
__device__ __forceinline__ void mbar_init(uint32_t mbar, uint32_t cnt) {
    asm volatile("mbarrier.init.shared.b64 [%0], %1;" :: "r"(mbar), "r"(cnt) : "memory");
}
__device__ __forceinline__ void mbar_expect_tx(uint32_t mbar, uint32_t bytes) {
    asm volatile("mbarrier.arrive.expect_tx.shared.b64 _, [%0], %1;"
                 :: "r"(mbar), "r"(bytes) : "memory");
}
__device__ __forceinline__ void mbar_wait(uint32_t mbar, uint32_t parity) {
    uint32_t done;
    asm volatile(
        "{\n\t.reg .pred p;\n\t"
        "mbarrier.try_wait.parity.acquire.cta.shared::cta.b64 p, [%1], %2;\n\t"
        "selp.b32 %0, 1, 0, p;\n\t}"
        : "=r"(done) : "r"(mbar), "r"(parity) : "memory");
    if (!done) {
        asm volatile(
            "{\n\t.reg .pred P1;\n\t"
            "W_%=:\n\t"
            "mbarrier.try_wait.parity.acquire.cta.shared::cta.b64 P1, [%0], %1, 0x989680;\n\t"
            "@P1 bra.uni DONE_%=;\n\t"
            "bra.uni W_%=;\n\t"
            "DONE_%=:\n\t}"
            :: "r"(mbar), "r"(parity) : "memory");
    }
}
__device__ __forceinline__ void bulk_copy(uint32_t dst_smem, const void* src,
                                          uint32_t bytes, uint32_t mbar) {
    asm volatile(
        "cp.async.bulk.shared::cluster.global.mbarrier::complete_tx::bytes "
        "[%0], [%1], %2, [%3];"
        :: "r"(dst_smem), "l"(src), "r"(bytes), "r"(mbar) : "memory");
}

// ---------------- W transpose prologue ----------------
__global__ void __launch_bounds__(1024)
transposeW_kernel(const float* __restrict__ W_in, const float* __restrict__ W_out)
{
    __shared__ float t[32][33];
    const int b = blockIdx.x;                         // 0..79
    const float* src = (b < 40) ? (W_out + b * 1024) : (W_in + (b - 40) * 1024);
    float* dst = g_Wt + b * 1024;
    const int c = threadIdx.x & 31;
    const int r = threadIdx.x >> 5;
    t[r][c] = src[r * 32 + c];       // t[d][e] = W[d][e]
    __syncthreads();
    dst[r * 32 + c] = t[c][r];       // Wt[e][d] = W[d][e]
}

// ---------------- main fused kernel ----------------
__global__ void __launch_bounds__(NTHREADS, 1)
graphlayer_kernel(const float* __restrict__ g,
                  const float* __restrict__ h,
                  const float* __restrict__ bias_p,
                  float* __restrict__ out)
{
    extern __shared__ float smem[];
    float* h_s  = smem + OH;
    float* hoag = smem + OHO;
    float* g_s  = smem + OG;

    const int tid  = threadIdx.x;
    const int lane = tid & 31;
    const int warp = tid >> 5;          // 0..15
    const long b0  = (long)blockIdx.x * NB;

    const uint32_t mb_h  = smem_u32(smem + OMB);
    const uint32_t mb_g1 = mb_h + 8;
    const uint32_t mb_g2 = mb_h + 16;

    if (tid == 0) {
        mbar_init(mb_h, 1);
        mbar_init(mb_g1, 1);
        mbar_init(mb_g2, 1);
    }
    __syncthreads();

    if (tid == 0) {
        // h: 16 rows of 5120B into padded smem rows
        mbar_expect_tx(mb_h, NB * F * D * 4);
        const uint32_t hdst = smem_u32(h_s);
        #pragma unroll
        for (int j = 0; j < NB; j++)
            bulk_copy(hdst + j * HSTR * 4, h + (b0 + j) * (F * D), F * D * 4, mb_h);
        // g chunk 1 (j = 0..7)
        mbar_expect_tx(mb_g1, 8 * F * F * 4);
        const uint32_t gdst = smem_u32(g_s);
        #pragma unroll
        for (int j = 0; j < 8; j++)
            bulk_copy(gdst + j * GSTR * 4, g + (b0 + j) * (F * F), F * F * 4, mb_g1);
    }

    const float* WoutT = g_Wt;
    const float* WinT  = g_Wt + 40 * 1024;

    const int fw = warp >> 1;           // 0..7 (field group)
    const int jh = warp & 1;            // 0/1  (batch half)
    const int jg = lane >> 3;           // 0..3
    const int dg = lane & 7;            // 0..7 (d quad)

    mbar_wait(mb_h, 0);

    // ---------------- Stage 1: hout[j][f][d] = sum_e Wout[f][d][e] h[j][f][e] ----------------
    #pragma unroll 1
    for (int k = 0; k < 5; k++) {
        const int f = fw + k * 8;
        const float* wt = WoutT + f * 1024 + dg * 4;
        unsigned long long acc[2][2] = {};
        #pragma unroll
        for (int e4 = 0; e4 < 8; e4++) {
            float4 hv[2];
            #pragma unroll
            for (int jt = 0; jt < 2; jt++)
                hv[jt] = *(const float4*)&h_s[(jg + 4 * jt + 8 * jh) * HSTR + f * 32 + e4 * 4];
            #pragma unroll
            for (int ee = 0; ee < 4; ee++) {
                const ulonglong2 w2 = __ldg((const ulonglong2*)(wt + (e4 * 4 + ee) * 32));
                #pragma unroll
                for (int jt = 0; jt < 2; jt++) {
                    const unsigned long long xd = pack2(((const float*)&hv[jt])[ee]);
                    acc[jt][0] = ffma2(xd, w2.x, acc[jt][0]);
                    acc[jt][1] = ffma2(xd, w2.y, acc[jt][1]);
                }
            }
        }
        #pragma unroll
        for (int jt = 0; jt < 2; jt++)
            *(ulonglong2*)&hoag[(jg + 4 * jt + 8 * jh) * HOSTR + f * 32 + dg * 4] =
                make_ulonglong2(acc[jt][0], acc[jt][1]);
    }
    __syncthreads();

    // prefetch g chunk 2 into the (now free) h region
    if (tid == 0) {
        mbar_expect_tx(mb_g2, 8 * F * F * 4);
        const uint32_t gdst2 = smem_u32(h_s);
        #pragma unroll
        for (int j = 0; j < 8; j++)
            bulk_copy(gdst2 + j * GSTR * 4, g + (b0 + 8 + j) * (F * F), F * F * 4, mb_g2);
    }

    // ---------------- Stage 2: aggr[j][f][d] = sum_gi g[j][f][gi] hout[j][gi][d] ----------------
    // warp = batch j (16 warps); lanes: fg = f group (0..3), dm = d-pair (0..7)
    {
        const int j = warp;
        if (j < 8) mbar_wait(mb_g1, 0);
        else       mbar_wait(mb_g2, 0);
        const float* gj  = (j < 8 ? g_s + j * GSTR : h_s + (j - 8) * GSTR);
        float*       hob = hoag + j * HOSTR;
        const int fg = lane >> 3;
        const int dm = lane & 7;

        unsigned long long acc[10][2];
        #pragma unroll
        for (int ft = 0; ft < 10; ft++) { acc[ft][0] = 0ull; acc[ft][1] = 0ull; }

        #pragma unroll 2
        for (int gq = 0; gq < 10; gq++) {
            unsigned long long ho0[4], ho1[4];
            #pragma unroll
            for (int t = 0; t < 4; t++) {
                ho0[t] = *(const unsigned long long*)(hob + (gq * 4 + t) * 32 + dm * 2);
                ho1[t] = *(const unsigned long long*)(hob + (gq * 4 + t) * 32 + dm * 2 + 16);
            }
            #pragma unroll
            for (int ft = 0; ft < 10; ft++) {
                const float4 g4 = *(const float4*)(gj + (fg + 4 * ft) * F + gq * 4);
                acc[ft][0] = ffma2(pack2(g4.x), ho0[0], acc[ft][0]);
                acc[ft][1] = ffma2(pack2(g4.x), ho1[0], acc[ft][1]);
                acc[ft][0] = ffma2(pack2(g4.y), ho0[1], acc[ft][0]);
                acc[ft][1] = ffma2(pack2(g4.y), ho1[1], acc[ft][1]);
                acc[ft][0] = ffma2(pack2(g4.z), ho0[2], acc[ft][0]);
                acc[ft][1] = ffma2(pack2(g4.z), ho1[2], acc[ft][1]);
                acc[ft][0] = ffma2(pack2(g4.w), ho0[3], acc[ft][0]);
                acc[ft][1] = ffma2(pack2(g4.w), ho1[3], acc[ft][1]);
            }
        }
        // write aggr in place (row jj fully consumed; only this warp owns it)
        #pragma unroll
        for (int ft = 0; ft < 10; ft++) {
            const int f = fg + 4 * ft;
            *(unsigned long long*)(hob + f * AFS + dm * 2)      = acc[ft][0];
            *(unsigned long long*)(hob + f * AFS + dm * 2 + 16) = acc[ft][1];
        }
    }
    __syncthreads();

    // ---------------- Stage 3: out[j][f][d] = sum_e Win[f][d][e] aggr[j][f][e] + bias ----------------
    const float4 bias4 = __ldg((const float4*)(bias_p + dg * 4));
    const unsigned long long b2lo = *(const unsigned long long*)&bias4.x;
    const unsigned long long b2hi = *(const unsigned long long*)&bias4.z;
    #pragma unroll 1
    for (int k = 0; k < 5; k++) {
        const int f = fw + k * 8;
        const float* wt = WinT + f * 1024 + dg * 4;
        unsigned long long acc[2][2];
        #pragma unroll
        for (int jt = 0; jt < 2; jt++) { acc[jt][0] = b2lo; acc[jt][1] = b2hi; }
        #pragma unroll
        for (int e4 = 0; e4 < 8; e4++) {
            float4 av[2];
            #pragma unroll
            for (int jt = 0; jt < 2; jt++)
                av[jt] = *(const float4*)&hoag[(jg + 4 * jt + 8 * jh) * HOSTR + f * AFS + e4 * 4];
            #pragma unroll
            for (int ee = 0; ee < 4; ee++) {
                const ulonglong2 w2 = __ldg((const ulonglong2*)(wt + (e4 * 4 + ee) * 32));
                #pragma unroll
                for (int jt = 0; jt < 2; jt++) {
                    const unsigned long long xd = pack2(((const float*)&av[jt])[ee]);
                    acc[jt][0] = ffma2(xd, w2.x, acc[jt][0]);
                    acc[jt][1] = ffma2(xd, w2.y, acc[jt][1]);
                }
            }
        }
        #pragma unroll
        for (int jt = 0; jt < 2; jt++) {
            const int j = jg + 4 * jt + 8 * jh;
            *(ulonglong2*)&out[(b0 + j) * (F * D) + f * 32 + dg * 4] =
                make_ulonglong2(acc[jt][0], acc[jt][1]);
        }
    }
}

extern "C" void kernel_launch(void* const* d_in, const int* in_sizes, int n_in,
                              void* d_out, int out_size)
{
    (void)in_sizes; (void)n_in; (void)out_size;
    const float* g     = (const float*)d_in[0];
    const float* h     = (const float*)d_in[1];
    const float* W_in  = (const float*)d_in[2];
    const float* W_out = (const float*)d_in[3];
    const float* bias  = (const float*)d_in[4];
    float* out = (float*)d_out;

    cudaFuncSetAttribute(graphlayer_kernel,
                         cudaFuncAttributeMaxDynamicSharedMemorySize, SMEM_BYTES);

    transposeW_kernel<<<80, 1024>>>(W_in, W_out);
    graphlayer_kernel<<<GRID, NTHREADS, SMEM_BYTES>>>(g, h, bias, out);
}